// round 15
// baseline (speedup 1.0000x reference)
#include <cuda_runtime.h>
#include <cuda_bf16.h>
#include <cuda_fp16.h>
#include <math.h>

#define F_DIM   128
#define HEADS   8
#define CH      16
#define MAXN    50048
#define MAXE    860160

// ---------------- device scratch ----------------
__device__ __half g_hh[MAXN * F_DIM];    // GEMM output in fp16 (gather-optimized)
__device__ float g_t[MAXN * F_DIM];      // layer0 aggregated output (fp32)
__device__ float g_asrc[MAXN * HEADS];
__device__ float g_adst[MAXN * HEADS];
__device__ int   g_deg[MAXN];
__device__ int   g_off[MAXN + 1];
__device__ int   g_cur[MAXN];
__device__ int   g_csr[MAXE];
__device__ float g_pool[MAXN * CH];
__device__ float g_bnsum0[F_DIM];
__device__ float g_bnsq0[F_DIM];
__device__ float g_bnsum1[CH];
__device__ float g_bnsq1[CH];
__device__ float g_bnscale[F_DIM];
__device__ float g_bnshift[F_DIM];

// ---------------- utility kernels ----------------
__global__ void zero_ints(int* p, int n) {
    int i = blockIdx.x * blockDim.x + threadIdx.x;
    if (i < n) p[i] = 0;
}
__global__ void zero_bn_all() {   // zero both layers' stats in one launch
    int i = threadIdx.x;
    if (i < F_DIM) { g_bnsum0[i] = 0.f; g_bnsq0[i] = 0.f; }
    if (i < CH)    { g_bnsum1[i] = 0.f; g_bnsq1[i] = 0.f; }
}

// ---------------- CSR build ----------------
__global__ void hist_kernel(const int* __restrict__ ei, int E, int n) {
    int i = blockIdx.x * blockDim.x + threadIdx.x;
    int tot = E + n;
    if (i >= tot) return;
    int d = (i < E) ? ei[E + i] : (i - E);
    atomicAdd(&g_deg[d], 1);
}

// two-level shfl scan, 1024 threads
__global__ void scan_kernel(int n) {
    __shared__ int wsum[32];
    int tid = threadIdx.x;
    int lane = tid & 31, wid = tid >> 5;
    int chunk = (n + 1023) >> 10;
    int b = tid * chunk;
    int e = min(n, b + chunk);
    int s = 0;
    for (int i = b; i < e; i++) s += g_deg[i];
    int v = s;
#pragma unroll
    for (int o = 1; o < 32; o <<= 1) {
        int t = __shfl_up_sync(0xFFFFFFFFu, v, o);
        if (lane >= o) v += t;
    }
    if (lane == 31) wsum[wid] = v;
    __syncthreads();
    if (wid == 0) {
        int w = wsum[lane];
#pragma unroll
        for (int o = 1; o < 32; o <<= 1) {
            int t = __shfl_up_sync(0xFFFFFFFFu, w, o);
            if (lane >= o) w += t;
        }
        wsum[lane] = w;
    }
    __syncthreads();
    int excl = v - s + ((wid > 0) ? wsum[wid - 1] : 0);
    int run = excl;
    for (int i = b; i < e; i++) {
        g_off[i] = run;
        g_cur[i] = run;
        run += g_deg[i];
    }
    if (tid == 0) g_off[n] = wsum[31];
}

__global__ void scatter_kernel(const int* __restrict__ ei, int E, int n) {
    int i = blockIdx.x * blockDim.x + threadIdx.x;
    int tot = E + n;
    if (i >= tot) return;
    int s, d;
    if (i < E) { s = ei[i]; d = ei[E + i]; }
    else       { s = d = i - E; }
    int p = atomicAdd(&g_cur[d], 1);
    g_csr[p] = s;
}

// ---------------- fused GEMM + attention-score epilogue (R11 proven version) --
__device__ __forceinline__ float bnelu_f(float v, int f) {
    float y = v * g_bnscale[f] + g_bnshift[f];
    return (y > 0.f) ? y : expm1f(y);
}

// smem: Bs fp32 [128*128] (64KB) + As fp32 [16*128] (8KB) = 72KB
#define GEMM_SMEM ((128 * 128 + 16 * 128) * (int)sizeof(float))

template <bool BNELU>
__global__ __launch_bounds__(256, 2) void gemm_fused(
    const float* __restrict__ A, const float* __restrict__ B,
    __half* __restrict__ Ch,
    const float* __restrict__ attS, const float* __restrict__ attD, int M)
{
    extern __shared__ float smem[];
    float* Bs = smem;                 // [128][128]
    float* As = smem + 128 * 128;     // [16][128]
    int tid = threadIdx.x;
    int row0 = blockIdx.x * 128;
    int tr = (tid >> 4) * 8;
    int tc = (tid & 15) * 8;

    // load full B into smem (issued before first barrier)
    for (int i = tid * 4; i < 128 * 128; i += 1024) {
        *(float4*)(Bs + i) = *(const float4*)(B + i);
    }

    int ar = tid >> 1;
    int ak = (tid & 1) * 8;
    int arow = row0 + ar;
    bool aval = arow < M;
    const float* Aptr = A + (size_t)arow * F_DIM;

    float4 pa0 = make_float4(0.f, 0.f, 0.f, 0.f), pa1 = pa0;
    if (aval) {
        pa0 = *(const float4*)(Aptr + ak);
        pa1 = *(const float4*)(Aptr + ak + 4);
        if (BNELU) {
            pa0.x = bnelu_f(pa0.x, ak + 0); pa0.y = bnelu_f(pa0.y, ak + 1);
            pa0.z = bnelu_f(pa0.z, ak + 2); pa0.w = bnelu_f(pa0.w, ak + 3);
            pa1.x = bnelu_f(pa1.x, ak + 4); pa1.y = bnelu_f(pa1.y, ak + 5);
            pa1.z = bnelu_f(pa1.z, ak + 6); pa1.w = bnelu_f(pa1.w, ak + 7);
        }
    }

    float acc[8][8];
#pragma unroll
    for (int i = 0; i < 8; i++)
#pragma unroll
        for (int j = 0; j < 8; j++) acc[i][j] = 0.f;

#pragma unroll 1
    for (int c = 0; c < 8; c++) {
        __syncthreads();
        As[(ak + 0) * 128 + ar] = pa0.x;
        As[(ak + 1) * 128 + ar] = pa0.y;
        As[(ak + 2) * 128 + ar] = pa0.z;
        As[(ak + 3) * 128 + ar] = pa0.w;
        As[(ak + 4) * 128 + ar] = pa1.x;
        As[(ak + 5) * 128 + ar] = pa1.y;
        As[(ak + 6) * 128 + ar] = pa1.z;
        As[(ak + 7) * 128 + ar] = pa1.w;
        __syncthreads();
        if (c < 7 && aval) {
            int k0 = (c + 1) * 16;
            pa0 = *(const float4*)(Aptr + k0 + ak);
            pa1 = *(const float4*)(Aptr + k0 + ak + 4);
            if (BNELU) {
                pa0.x = bnelu_f(pa0.x, k0 + ak + 0); pa0.y = bnelu_f(pa0.y, k0 + ak + 1);
                pa0.z = bnelu_f(pa0.z, k0 + ak + 2); pa0.w = bnelu_f(pa0.w, k0 + ak + 3);
                pa1.x = bnelu_f(pa1.x, k0 + ak + 4); pa1.y = bnelu_f(pa1.y, k0 + ak + 5);
                pa1.z = bnelu_f(pa1.z, k0 + ak + 6); pa1.w = bnelu_f(pa1.w, k0 + ak + 7);
            }
        }
#pragma unroll
        for (int k = 0; k < 16; k++) {
            const float* asr = As + k * 128;
            const float* bsr = Bs + (c * 16 + k) * 128;
            float4 a0 = *(const float4*)(asr + tr);
            float4 a1 = *(const float4*)(asr + tr + 4);
            float4 b0 = *(const float4*)(bsr + tc);
            float4 b1 = *(const float4*)(bsr + tc + 4);
            float ra[8] = {a0.x, a0.y, a0.z, a0.w, a1.x, a1.y, a1.z, a1.w};
            float rb[8] = {b0.x, b0.y, b0.z, b0.w, b1.x, b1.y, b1.z, b1.w};
#pragma unroll
            for (int i = 0; i < 8; i++)
#pragma unroll
                for (int j = 0; j < 8; j++) acc[i][j] += ra[i] * rb[j];
        }
    }

    // epilogue: write C (fp16) and head-wise attention partial dots (fp32)
    int head = tc >> 4;
    int off = tc & 15;   // 0 or 8
    float as8[8], ad8[8];
#pragma unroll
    for (int j = 0; j < 8; j++) {
        as8[j] = __ldg(attS + head * CH + off + j);
        ad8[j] = __ldg(attD + head * CH + off + j);
    }
#pragma unroll
    for (int i = 0; i < 8; i++) {
        int r = row0 + tr + i;
        float s = 0.f, d = 0.f;
#pragma unroll
        for (int j = 0; j < 8; j++) {
            s += acc[i][j] * as8[j];
            d += acc[i][j] * ad8[j];
        }
        s += __shfl_xor_sync(0xFFFFFFFFu, s, 1);
        d += __shfl_xor_sync(0xFFFFFFFFu, d, 1);
        if (r < M) {
            __half2 p0 = __floats2half2_rn(acc[i][0], acc[i][1]);
            __half2 p1 = __floats2half2_rn(acc[i][2], acc[i][3]);
            __half2 p2 = __floats2half2_rn(acc[i][4], acc[i][5]);
            __half2 p3 = __floats2half2_rn(acc[i][6], acc[i][7]);
            uint4 pk;
            pk.x = *(unsigned*)&p0; pk.y = *(unsigned*)&p1;
            pk.z = *(unsigned*)&p2; pk.w = *(unsigned*)&p3;
            *(uint4*)(Ch + (size_t)r * F_DIM + tc) = pk;
            if (!(tid & 1)) {
                g_asrc[r * HEADS + head] = s;
                g_adst[r * HEADS + head] = d;
            }
        }
    }
}

// ---------------- single-pass softmax + aggregation + fused BN stats ----------
// warp per node; block = 8 nodes; BN sum/sumsq block-reduced in smem then
// one global atomicAdd per feature per block.
template <bool MEAN_HEADS>
__global__ void agg_kernel(const __half* __restrict__ h,
                           const float* __restrict__ bias,
                           float* __restrict__ out, int n) {
    __shared__ float s_sum[MEAN_HEADS ? CH : F_DIM];
    __shared__ float s_sq[MEAN_HEADS ? CH : F_DIM];
    const int NF = MEAN_HEADS ? CH : F_DIM;
    int tid = threadIdx.x;
    if (tid < NF) { s_sum[tid] = 0.f; s_sq[tid] = 0.f; }
    __syncthreads();

    int warp = (blockIdx.x * blockDim.x + tid) >> 5;
    int lane = tid & 31;
    int node = warp;
    int head = lane >> 2;
    int fo = lane * 4;

    if (node < n) {
        int beg = g_off[node];
        int end = g_off[node + 1];
        float adst_v = g_adst[node * HEADS + head];

        float ssum = 0.f;
        float4 acc = make_float4(0.f, 0.f, 0.f, 0.f);
        for (int i = beg; i < end; i++) {
            int s = g_csr[i];
            float e = g_asrc[s * HEADS + head] + adst_v;
            e = (e > 0.f) ? e : 0.2f * e;
            float w = __expf(e);
            ssum += w;
            uint2 raw = *(const uint2*)(h + (size_t)s * F_DIM + fo);
            float2 f01 = __half22float2(*(__half2*)&raw.x);
            float2 f23 = __half22float2(*(__half2*)&raw.y);
            acc.x += w * f01.x;
            acc.y += w * f01.y;
            acc.z += w * f23.x;
            acc.w += w * f23.y;
        }
        float inv = 1.0f / (ssum + 1e-16f);
        acc.x *= inv; acc.y *= inv; acc.z *= inv; acc.w *= inv;

        if (MEAN_HEADS) {
#pragma unroll
            for (int o = 4; o < 32; o <<= 1) {
                acc.x += __shfl_xor_sync(0xFFFFFFFFu, acc.x, o);
                acc.y += __shfl_xor_sync(0xFFFFFFFFu, acc.y, o);
                acc.z += __shfl_xor_sync(0xFFFFFFFFu, acc.z, o);
                acc.w += __shfl_xor_sync(0xFFFFFFFFu, acc.w, o);
            }
            if (lane < 4) {
                int cbase = lane * 4;
                float4 r;
                r.x = acc.x * 0.125f + __ldg(&bias[cbase + 0]);
                r.y = acc.y * 0.125f + __ldg(&bias[cbase + 1]);
                r.z = acc.z * 0.125f + __ldg(&bias[cbase + 2]);
                r.w = acc.w * 0.125f + __ldg(&bias[cbase + 3]);
                *(float4*)(out + (size_t)node * CH + cbase) = r;
                atomicAdd(&s_sum[cbase + 0], r.x);
                atomicAdd(&s_sum[cbase + 1], r.y);
                atomicAdd(&s_sum[cbase + 2], r.z);
                atomicAdd(&s_sum[cbase + 3], r.w);
                atomicAdd(&s_sq[cbase + 0], r.x * r.x);
                atomicAdd(&s_sq[cbase + 1], r.y * r.y);
                atomicAdd(&s_sq[cbase + 2], r.z * r.z);
                atomicAdd(&s_sq[cbase + 3], r.w * r.w);
            }
        } else {
            float4 r;
            r.x = acc.x + __ldg(&bias[fo + 0]);
            r.y = acc.y + __ldg(&bias[fo + 1]);
            r.z = acc.z + __ldg(&bias[fo + 2]);
            r.w = acc.w + __ldg(&bias[fo + 3]);
            *(float4*)(out + (size_t)node * F_DIM + fo) = r;
            atomicAdd(&s_sum[fo + 0], r.x);
            atomicAdd(&s_sum[fo + 1], r.y);
            atomicAdd(&s_sum[fo + 2], r.z);
            atomicAdd(&s_sum[fo + 3], r.w);
            atomicAdd(&s_sq[fo + 0], r.x * r.x);
            atomicAdd(&s_sq[fo + 1], r.y * r.y);
            atomicAdd(&s_sq[fo + 2], r.z * r.z);
            atomicAdd(&s_sq[fo + 3], r.w * r.w);
        }
    }
    __syncthreads();
    if (tid < NF) {
        if (MEAN_HEADS) {
            atomicAdd(&g_bnsum1[tid], s_sum[tid]);
            atomicAdd(&g_bnsq1[tid], s_sq[tid]);
        } else {
            atomicAdd(&g_bnsum0[tid], s_sum[tid]);
            atomicAdd(&g_bnsq0[tid], s_sq[tid]);
        }
    }
}

// ---------------- BN finalize: precompute scale/shift (layer0) ----------------
__global__ void bn_finalize(const float* __restrict__ gamma,
                            const float* __restrict__ beta, float invn) {
    int f = threadIdx.x;
    float mu = g_bnsum0[f] * invn;
    float var = g_bnsq0[f] * invn - mu * mu;
    float sc = rsqrtf(var + 1e-5f) * gamma[f];
    g_bnscale[f] = sc;
    g_bnshift[f] = beta[f] - mu * sc;
}

// ---------------- final: BN(F=16) + classifier [16x2] ----------------
__global__ void final_kernel(const float* __restrict__ gamma,
                             const float* __restrict__ beta,
                             const float* __restrict__ Wc,
                             const float* __restrict__ bc,
                             float* __restrict__ out, int n, float invn) {
    int node = blockIdx.x * blockDim.x + threadIdx.x;
    if (node >= n) return;
    float l0 = __ldg(&bc[0]);
    float l1 = __ldg(&bc[1]);
#pragma unroll
    for (int c = 0; c < CH; c++) {
        float mu = g_bnsum1[c] * invn;
        float var = g_bnsq1[c] * invn - mu * mu;
        float sc = rsqrtf(var + 1e-5f) * __ldg(&gamma[c]);
        float y = (g_pool[(size_t)node * CH + c] - mu) * sc + __ldg(&beta[c]);
        l0 += y * __ldg(&Wc[c * 2 + 0]);
        l1 += y * __ldg(&Wc[c * 2 + 1]);
    }
    out[node * 2 + 0] = l0;
    out[node * 2 + 1] = l1;
}

// ---------------- launch ----------------
extern "C" void kernel_launch(void* const* d_in, const int* in_sizes, int n_in,
                              void* d_out, int out_size) {
    const float* x        = (const float*)d_in[0];
    const int*   ei       = (const int*)d_in[1];
    const float* W0       = (const float*)d_in[2];
    const float* att_src0 = (const float*)d_in[3];
    const float* att_dst0 = (const float*)d_in[4];
    const float* b0       = (const float*)d_in[5];
    const float* gamma0   = (const float*)d_in[6];
    const float* beta0    = (const float*)d_in[7];
    const float* W1       = (const float*)d_in[8];
    const float* att_src1 = (const float*)d_in[9];
    const float* att_dst1 = (const float*)d_in[10];
    const float* b1       = (const float*)d_in[11];
    const float* gamma1   = (const float*)d_in[12];
    const float* beta1    = (const float*)d_in[13];
    const float* Wc       = (const float*)d_in[14];
    const float* bc       = (const float*)d_in[15];
    float* out = (float*)d_out;

    int N = in_sizes[0] / F_DIM;
    int E = in_sizes[1] / 2;
    int ET = E + N;
    float invn = 1.0f / (float)N;

    __half* g_hh_p;
    float *g_t_p, *g_pool_p;
    int *g_deg_p;
    cudaGetSymbolAddress((void**)&g_hh_p, g_hh);
    cudaGetSymbolAddress((void**)&g_t_p, g_t);
    cudaGetSymbolAddress((void**)&g_pool_p, g_pool);
    cudaGetSymbolAddress((void**)&g_deg_p, g_deg);

    cudaFuncSetAttribute(gemm_fused<false>,
                         cudaFuncAttributeMaxDynamicSharedMemorySize, GEMM_SMEM);
    cudaFuncSetAttribute(gemm_fused<true>,
                         cudaFuncAttributeMaxDynamicSharedMemorySize, GEMM_SMEM);

    int gemm_grid = (N + 127) / 128;

    // side stream for CSR build + stat zeroing, forked/joined with events
    cudaStream_t s2;
    cudaStreamCreateWithFlags(&s2, cudaStreamNonBlocking);
    cudaEvent_t evFork, evJoin;
    cudaEventCreateWithFlags(&evFork, cudaEventDisableTiming);
    cudaEventCreateWithFlags(&evJoin, cudaEventDisableTiming);

    cudaEventRecord(evFork, 0);
    cudaStreamWaitEvent(s2, evFork, 0);

    // ---- CSR build + BN-stat zero on side stream (independent of GEMM0) ----
    zero_ints<<<(N + 255) / 256, 256, 0, s2>>>(g_deg_p, N);
    zero_bn_all<<<1, 256, 0, s2>>>();
    hist_kernel<<<(ET + 255) / 256, 256, 0, s2>>>(ei, E, N);
    scan_kernel<<<1, 1024, 0, s2>>>(N);
    scatter_kernel<<<(ET + 255) / 256, 256, 0, s2>>>(ei, E, N);
    cudaEventRecord(evJoin, s2);

    // ---- layer 0: GEMM(+attn scores) on main stream, concurrent with CSR ----
    gemm_fused<false><<<gemm_grid, 256, GEMM_SMEM>>>(x, W0, g_hh_p,
                                                     att_src0, att_dst0, N);
    cudaStreamWaitEvent(0, evJoin, 0);   // join: agg needs CSR + zeroed stats
    agg_kernel<false><<<(N * 32 + 255) / 256, 256>>>(g_hh_p, b0, g_t_p, N);
    bn_finalize<<<1, F_DIM>>>(gamma0, beta0, invn);

    // ---- layer 1: GEMM with fused BN+ELU on A (+attn scores) -> agg ----
    gemm_fused<true><<<gemm_grid, 256, GEMM_SMEM>>>(g_t_p, W1, g_hh_p,
                                                    att_src1, att_dst1, N);
    agg_kernel<true><<<(N * 32 + 255) / 256, 256>>>(g_hh_p, b1, g_pool_p, N);
    final_kernel<<<(N + 255) / 256, 256>>>(gamma1, beta1, Wc, bc, out, N, invn);
    // streams/events intentionally not destroyed here: destroying capture-
    // participating resources mid-capture is illegal; leak is a few host handles
    // on the 2 non-replay calls.
}

// round 16
// speedup vs baseline: 1.2910x; 1.2910x over previous
#include <cuda_runtime.h>
#include <cuda_bf16.h>
#include <cuda_fp16.h>
#include <math.h>

#define F_DIM   128
#define HEADS   8
#define CH      16
#define MAXN    50048
#define MAXE    860160

// ---------------- device scratch ----------------
__device__ __half g_hh[MAXN * F_DIM];    // GEMM output in fp16 (gather-optimized)
__device__ float g_t[MAXN * F_DIM];      // layer0 aggregated output (fp32)
__device__ float g_asrc[MAXN * HEADS];
__device__ float g_adst[MAXN * HEADS];
__device__ int   g_deg[MAXN];
__device__ int   g_off[MAXN + 1];
__device__ int   g_cur[MAXN];
__device__ int   g_csr[MAXE];
__device__ int   g_bsum[256];
__device__ float g_pool[MAXN * CH];
__device__ float g_bnsum0[F_DIM];
__device__ float g_bnsq0[F_DIM];
__device__ float g_bnsum1[CH];
__device__ float g_bnsq1[CH];
__device__ float g_bnscale[F_DIM];
__device__ float g_bnshift[F_DIM];

// ---------------- utility kernels ----------------
__global__ void zero_ints(int* p, int n) {
    int i = blockIdx.x * blockDim.x + threadIdx.x;
    if (i < n) p[i] = 0;
}
__global__ void zero_bn_all() {
    int i = threadIdx.x;
    if (i < F_DIM) { g_bnsum0[i] = 0.f; g_bnsq0[i] = 0.f; }
    if (i < CH)    { g_bnsum1[i] = 0.f; g_bnsq1[i] = 0.f; }
}

// ---------------- CSR build ----------------
__global__ void hist_kernel(const int* __restrict__ ei, int E, int n) {
    int i = blockIdx.x * blockDim.x + threadIdx.x;
    int tot = E + n;
    if (i >= tot) return;
    int d = (i < E) ? ei[E + i] : (i - E);
    atomicAdd(&g_deg[d], 1);
}

// grid-parallel 3-phase exclusive scan over g_deg (n <= 65536)
__global__ void scan_p1(int n) {
    __shared__ int ws[8];
    int tid = threadIdx.x;
    int i = blockIdx.x * 256 + tid;
    int v = (i < n) ? g_deg[i] : 0;
    int s = v;
#pragma unroll
    for (int o = 16; o; o >>= 1) s += __shfl_xor_sync(0xFFFFFFFFu, s, o);
    if ((tid & 31) == 0) ws[tid >> 5] = s;
    __syncthreads();
    if (tid < 8) {
        int t = ws[tid];
#pragma unroll
        for (int o = 4; o; o >>= 1) t += __shfl_xor_sync(0xFFu, t, o);
        if (tid == 0) g_bsum[blockIdx.x] = t;
    }
}

__global__ void scan_p2(int nb, int n) {
    __shared__ int ws[8];
    int tid = threadIdx.x;
    int lane = tid & 31, wid = tid >> 5;
    int v = (tid < nb) ? g_bsum[tid] : 0;
    int incl = v;
#pragma unroll
    for (int o = 1; o < 32; o <<= 1) {
        int t = __shfl_up_sync(0xFFFFFFFFu, incl, o);
        if (lane >= o) incl += t;
    }
    if (lane == 31) ws[wid] = incl;
    __syncthreads();
    if (wid == 0) {
        int w = (lane < 8) ? ws[lane] : 0;
#pragma unroll
        for (int o = 1; o < 8; o <<= 1) {
            int t = __shfl_up_sync(0xFFFFFFFFu, w, o);
            if (lane >= o) w += t;
        }
        if (lane < 8) ws[lane] = w;
    }
    __syncthreads();
    int total_excl = incl - v + (wid ? ws[wid - 1] : 0);
    if (tid < nb) g_bsum[tid] = total_excl;
    if (tid == 255) g_off[n] = ws[7];   // grand total (inclusive of all warps)
}

__global__ void scan_p3(int n) {
    __shared__ int ws[8];
    int tid = threadIdx.x;
    int lane = tid & 31, wid = tid >> 5;
    int i = blockIdx.x * 256 + tid;
    int v = (i < n) ? g_deg[i] : 0;
    int incl = v;
#pragma unroll
    for (int o = 1; o < 32; o <<= 1) {
        int t = __shfl_up_sync(0xFFFFFFFFu, incl, o);
        if (lane >= o) incl += t;
    }
    if (lane == 31) ws[wid] = incl;
    __syncthreads();
    if (wid == 0) {
        int w = (lane < 8) ? ws[lane] : 0;
#pragma unroll
        for (int o = 1; o < 8; o <<= 1) {
            int t = __shfl_up_sync(0xFFFFFFFFu, w, o);
            if (lane >= o) w += t;
        }
        if (lane < 8) ws[lane] = w;
    }
    __syncthreads();
    int excl = incl - v + (wid ? ws[wid - 1] : 0) + g_bsum[blockIdx.x];
    if (i < n) { g_off[i] = excl; g_cur[i] = excl; }
}

__global__ void scatter_kernel(const int* __restrict__ ei, int E, int n) {
    int i = blockIdx.x * blockDim.x + threadIdx.x;
    int tot = E + n;
    if (i >= tot) return;
    int s, d;
    if (i < E) { s = ei[i]; d = ei[E + i]; }
    else       { s = d = i - E; }
    int p = atomicAdd(&g_cur[d], 1);
    g_csr[p] = s;
}

// ---------------- fused GEMM + attention-score epilogue ----------------
__device__ __forceinline__ float bnelu_f(float v, int f) {
    float y = v * g_bnscale[f] + g_bnshift[f];
    return (y > 0.f) ? y : expm1f(y);
}

#define GEMM_SMEM ((128 * 128 + 16 * 128) * (int)sizeof(float))

template <bool BNELU>
__global__ __launch_bounds__(256, 2) void gemm_fused(
    const float* __restrict__ A, const float* __restrict__ B,
    __half* __restrict__ Ch,
    const float* __restrict__ attS, const float* __restrict__ attD, int M)
{
    extern __shared__ float smem[];
    float* Bs = smem;                 // [128][128]
    float* As = smem + 128 * 128;     // [16][128]
    int tid = threadIdx.x;
    int row0 = blockIdx.x * 128;
    int tr = (tid >> 4) * 8;
    int tc = (tid & 15) * 8;

    for (int i = tid * 4; i < 128 * 128; i += 1024) {
        *(float4*)(Bs + i) = *(const float4*)(B + i);
    }

    int ar = tid >> 1;
    int ak = (tid & 1) * 8;
    int arow = row0 + ar;
    bool aval = arow < M;
    const float* Aptr = A + (size_t)arow * F_DIM;

    float4 pa0 = make_float4(0.f, 0.f, 0.f, 0.f), pa1 = pa0;
    if (aval) {
        pa0 = *(const float4*)(Aptr + ak);
        pa1 = *(const float4*)(Aptr + ak + 4);
        if (BNELU) {
            pa0.x = bnelu_f(pa0.x, ak + 0); pa0.y = bnelu_f(pa0.y, ak + 1);
            pa0.z = bnelu_f(pa0.z, ak + 2); pa0.w = bnelu_f(pa0.w, ak + 3);
            pa1.x = bnelu_f(pa1.x, ak + 4); pa1.y = bnelu_f(pa1.y, ak + 5);
            pa1.z = bnelu_f(pa1.z, ak + 6); pa1.w = bnelu_f(pa1.w, ak + 7);
        }
    }

    float acc[8][8];
#pragma unroll
    for (int i = 0; i < 8; i++)
#pragma unroll
        for (int j = 0; j < 8; j++) acc[i][j] = 0.f;

#pragma unroll 1
    for (int c = 0; c < 8; c++) {
        __syncthreads();
        As[(ak + 0) * 128 + ar] = pa0.x;
        As[(ak + 1) * 128 + ar] = pa0.y;
        As[(ak + 2) * 128 + ar] = pa0.z;
        As[(ak + 3) * 128 + ar] = pa0.w;
        As[(ak + 4) * 128 + ar] = pa1.x;
        As[(ak + 5) * 128 + ar] = pa1.y;
        As[(ak + 6) * 128 + ar] = pa1.z;
        As[(ak + 7) * 128 + ar] = pa1.w;
        __syncthreads();
        if (c < 7 && aval) {
            int k0 = (c + 1) * 16;
            pa0 = *(const float4*)(Aptr + k0 + ak);
            pa1 = *(const float4*)(Aptr + k0 + ak + 4);
            if (BNELU) {
                pa0.x = bnelu_f(pa0.x, k0 + ak + 0); pa0.y = bnelu_f(pa0.y, k0 + ak + 1);
                pa0.z = bnelu_f(pa0.z, k0 + ak + 2); pa0.w = bnelu_f(pa0.w, k0 + ak + 3);
                pa1.x = bnelu_f(pa1.x, k0 + ak + 4); pa1.y = bnelu_f(pa1.y, k0 + ak + 5);
                pa1.z = bnelu_f(pa1.z, k0 + ak + 6); pa1.w = bnelu_f(pa1.w, k0 + ak + 7);
            }
        }
#pragma unroll
        for (int k = 0; k < 16; k++) {
            const float* asr = As + k * 128;
            const float* bsr = Bs + (c * 16 + k) * 128;
            float4 a0 = *(const float4*)(asr + tr);
            float4 a1 = *(const float4*)(asr + tr + 4);
            float4 b0 = *(const float4*)(bsr + tc);
            float4 b1 = *(const float4*)(bsr + tc + 4);
            float ra[8] = {a0.x, a0.y, a0.z, a0.w, a1.x, a1.y, a1.z, a1.w};
            float rb[8] = {b0.x, b0.y, b0.z, b0.w, b1.x, b1.y, b1.z, b1.w};
#pragma unroll
            for (int i = 0; i < 8; i++)
#pragma unroll
                for (int j = 0; j < 8; j++) acc[i][j] += ra[i] * rb[j];
        }
    }

    int head = tc >> 4;
    int off = tc & 15;
    float as8[8], ad8[8];
#pragma unroll
    for (int j = 0; j < 8; j++) {
        as8[j] = __ldg(attS + head * CH + off + j);
        ad8[j] = __ldg(attD + head * CH + off + j);
    }
#pragma unroll
    for (int i = 0; i < 8; i++) {
        int r = row0 + tr + i;
        float s = 0.f, d = 0.f;
#pragma unroll
        for (int j = 0; j < 8; j++) {
            s += acc[i][j] * as8[j];
            d += acc[i][j] * ad8[j];
        }
        s += __shfl_xor_sync(0xFFFFFFFFu, s, 1);
        d += __shfl_xor_sync(0xFFFFFFFFu, d, 1);
        if (r < M) {
            __half2 p0 = __floats2half2_rn(acc[i][0], acc[i][1]);
            __half2 p1 = __floats2half2_rn(acc[i][2], acc[i][3]);
            __half2 p2 = __floats2half2_rn(acc[i][4], acc[i][5]);
            __half2 p3 = __floats2half2_rn(acc[i][6], acc[i][7]);
            uint4 pk;
            pk.x = *(unsigned*)&p0; pk.y = *(unsigned*)&p1;
            pk.z = *(unsigned*)&p2; pk.w = *(unsigned*)&p3;
            *(uint4*)(Ch + (size_t)r * F_DIM + tc) = pk;
            if (!(tid & 1)) {
                g_asrc[r * HEADS + head] = s;
                g_adst[r * HEADS + head] = d;
            }
        }
    }
}

// ---------------- single-pass softmax + aggregation + fused BN stats ----------
template <bool MEAN_HEADS>
__global__ void agg_kernel(const __half* __restrict__ h,
                           const float* __restrict__ bias,
                           float* __restrict__ out, int n) {
    __shared__ float s_sum[MEAN_HEADS ? CH : F_DIM];
    __shared__ float s_sq[MEAN_HEADS ? CH : F_DIM];
    const int NF = MEAN_HEADS ? CH : F_DIM;
    int tid = threadIdx.x;
    if (tid < NF) { s_sum[tid] = 0.f; s_sq[tid] = 0.f; }
    __syncthreads();

    int warp = (blockIdx.x * blockDim.x + tid) >> 5;
    int lane = tid & 31;
    int node = warp;
    int head = lane >> 2;
    int fo = lane * 4;

    if (node < n) {
        int beg = g_off[node];
        int end = g_off[node + 1];
        float adst_v = g_adst[node * HEADS + head];

        float ssum = 0.f;
        float4 acc = make_float4(0.f, 0.f, 0.f, 0.f);
        for (int i = beg; i < end; i++) {
            int s = g_csr[i];
            float e = g_asrc[s * HEADS + head] + adst_v;
            e = (e > 0.f) ? e : 0.2f * e;
            float w = __expf(e);
            ssum += w;
            uint2 raw = *(const uint2*)(h + (size_t)s * F_DIM + fo);
            float2 f01 = __half22float2(*(__half2*)&raw.x);
            float2 f23 = __half22float2(*(__half2*)&raw.y);
            acc.x += w * f01.x;
            acc.y += w * f01.y;
            acc.z += w * f23.x;
            acc.w += w * f23.y;
        }
        float inv = 1.0f / (ssum + 1e-16f);
        acc.x *= inv; acc.y *= inv; acc.z *= inv; acc.w *= inv;

        if (MEAN_HEADS) {
#pragma unroll
            for (int o = 4; o < 32; o <<= 1) {
                acc.x += __shfl_xor_sync(0xFFFFFFFFu, acc.x, o);
                acc.y += __shfl_xor_sync(0xFFFFFFFFu, acc.y, o);
                acc.z += __shfl_xor_sync(0xFFFFFFFFu, acc.z, o);
                acc.w += __shfl_xor_sync(0xFFFFFFFFu, acc.w, o);
            }
            if (lane < 4) {
                int cbase = lane * 4;
                float4 r;
                r.x = acc.x * 0.125f + __ldg(&bias[cbase + 0]);
                r.y = acc.y * 0.125f + __ldg(&bias[cbase + 1]);
                r.z = acc.z * 0.125f + __ldg(&bias[cbase + 2]);
                r.w = acc.w * 0.125f + __ldg(&bias[cbase + 3]);
                *(float4*)(out + (size_t)node * CH + cbase) = r;
                atomicAdd(&s_sum[cbase + 0], r.x);
                atomicAdd(&s_sum[cbase + 1], r.y);
                atomicAdd(&s_sum[cbase + 2], r.z);
                atomicAdd(&s_sum[cbase + 3], r.w);
                atomicAdd(&s_sq[cbase + 0], r.x * r.x);
                atomicAdd(&s_sq[cbase + 1], r.y * r.y);
                atomicAdd(&s_sq[cbase + 2], r.z * r.z);
                atomicAdd(&s_sq[cbase + 3], r.w * r.w);
            }
        } else {
            float4 r;
            r.x = acc.x + __ldg(&bias[fo + 0]);
            r.y = acc.y + __ldg(&bias[fo + 1]);
            r.z = acc.z + __ldg(&bias[fo + 2]);
            r.w = acc.w + __ldg(&bias[fo + 3]);
            *(float4*)(out + (size_t)node * F_DIM + fo) = r;
            atomicAdd(&s_sum[fo + 0], r.x);
            atomicAdd(&s_sum[fo + 1], r.y);
            atomicAdd(&s_sum[fo + 2], r.z);
            atomicAdd(&s_sum[fo + 3], r.w);
            atomicAdd(&s_sq[fo + 0], r.x * r.x);
            atomicAdd(&s_sq[fo + 1], r.y * r.y);
            atomicAdd(&s_sq[fo + 2], r.z * r.z);
            atomicAdd(&s_sq[fo + 3], r.w * r.w);
        }
    }
    __syncthreads();
    if (tid < NF) {
        if (MEAN_HEADS) {
            atomicAdd(&g_bnsum1[tid], s_sum[tid]);
            atomicAdd(&g_bnsq1[tid], s_sq[tid]);
        } else {
            atomicAdd(&g_bnsum0[tid], s_sum[tid]);
            atomicAdd(&g_bnsq0[tid], s_sq[tid]);
        }
    }
}

// ---------------- BN finalize: precompute scale/shift (layer0) ----------------
__global__ void bn_finalize(const float* __restrict__ gamma,
                            const float* __restrict__ beta, float invn) {
    int f = threadIdx.x;
    float mu = g_bnsum0[f] * invn;
    float var = g_bnsq0[f] * invn - mu * mu;
    float sc = rsqrtf(var + 1e-5f) * gamma[f];
    g_bnscale[f] = sc;
    g_bnshift[f] = beta[f] - mu * sc;
}

// ---------------- final: BN(F=16) + classifier [16x2] ----------------
__global__ void final_kernel(const float* __restrict__ gamma,
                             const float* __restrict__ beta,
                             const float* __restrict__ Wc,
                             const float* __restrict__ bc,
                             float* __restrict__ out, int n, float invn) {
    int node = blockIdx.x * blockDim.x + threadIdx.x;
    if (node >= n) return;
    float l0 = __ldg(&bc[0]);
    float l1 = __ldg(&bc[1]);
#pragma unroll
    for (int c = 0; c < CH; c++) {
        float mu = g_bnsum1[c] * invn;
        float var = g_bnsq1[c] * invn - mu * mu;
        float sc = rsqrtf(var + 1e-5f) * __ldg(&gamma[c]);
        float y = (g_pool[(size_t)node * CH + c] - mu) * sc + __ldg(&beta[c]);
        l0 += y * __ldg(&Wc[c * 2 + 0]);
        l1 += y * __ldg(&Wc[c * 2 + 1]);
    }
    out[node * 2 + 0] = l0;
    out[node * 2 + 1] = l1;
}

// ---------------- launch ----------------
extern "C" void kernel_launch(void* const* d_in, const int* in_sizes, int n_in,
                              void* d_out, int out_size) {
    const float* x        = (const float*)d_in[0];
    const int*   ei       = (const int*)d_in[1];
    const float* W0       = (const float*)d_in[2];
    const float* att_src0 = (const float*)d_in[3];
    const float* att_dst0 = (const float*)d_in[4];
    const float* b0       = (const float*)d_in[5];
    const float* gamma0   = (const float*)d_in[6];
    const float* beta0    = (const float*)d_in[7];
    const float* W1       = (const float*)d_in[8];
    const float* att_src1 = (const float*)d_in[9];
    const float* att_dst1 = (const float*)d_in[10];
    const float* b1       = (const float*)d_in[11];
    const float* gamma1   = (const float*)d_in[12];
    const float* beta1    = (const float*)d_in[13];
    const float* Wc       = (const float*)d_in[14];
    const float* bc       = (const float*)d_in[15];
    float* out = (float*)d_out;

    int N = in_sizes[0] / F_DIM;
    int E = in_sizes[1] / 2;
    int ET = E + N;
    int NB = (N + 255) / 256;   // <= 256 for N <= 65536
    float invn = 1.0f / (float)N;

    __half* g_hh_p;
    float *g_t_p, *g_pool_p;
    int *g_deg_p;
    cudaGetSymbolAddress((void**)&g_hh_p, g_hh);
    cudaGetSymbolAddress((void**)&g_t_p, g_t);
    cudaGetSymbolAddress((void**)&g_pool_p, g_pool);
    cudaGetSymbolAddress((void**)&g_deg_p, g_deg);

    cudaFuncSetAttribute(gemm_fused<false>,
                         cudaFuncAttributeMaxDynamicSharedMemorySize, GEMM_SMEM);
    cudaFuncSetAttribute(gemm_fused<true>,
                         cudaFuncAttributeMaxDynamicSharedMemorySize, GEMM_SMEM);

    int gemm_grid = (N + 127) / 128;

    // side stream for CSR build + stat zeroing, forked/joined with events
    cudaStream_t s2;
    cudaStreamCreateWithFlags(&s2, cudaStreamNonBlocking);
    cudaEvent_t evFork, evJoin;
    cudaEventCreateWithFlags(&evFork, cudaEventDisableTiming);
    cudaEventCreateWithFlags(&evJoin, cudaEventDisableTiming);

    cudaEventRecord(evFork, 0);
    cudaStreamWaitEvent(s2, evFork, 0);

    // ---- CSR build + BN-stat zero on side stream (independent of GEMM0) ----
    zero_ints<<<(N + 255) / 256, 256, 0, s2>>>(g_deg_p, N);
    zero_bn_all<<<1, 256, 0, s2>>>();
    hist_kernel<<<(ET + 255) / 256, 256, 0, s2>>>(ei, E, N);
    scan_p1<<<NB, 256, 0, s2>>>(N);
    scan_p2<<<1, 256, 0, s2>>>(NB, N);
    scan_p3<<<NB, 256, 0, s2>>>(N);
    scatter_kernel<<<(ET + 255) / 256, 256, 0, s2>>>(ei, E, N);
    cudaEventRecord(evJoin, s2);

    // ---- layer 0: GEMM(+attn scores) on main stream, concurrent with CSR ----
    gemm_fused<false><<<gemm_grid, 256, GEMM_SMEM>>>(x, W0, g_hh_p,
                                                     att_src0, att_dst0, N);
    cudaStreamWaitEvent(0, evJoin, 0);   // join: agg needs CSR + zeroed stats
    agg_kernel<false><<<(N * 32 + 255) / 256, 256>>>(g_hh_p, b0, g_t_p, N);
    bn_finalize<<<1, F_DIM>>>(gamma0, beta0, invn);

    // ---- layer 1: GEMM with fused BN+ELU on A (+attn scores) -> agg ----
    gemm_fused<true><<<gemm_grid, 256, GEMM_SMEM>>>(g_t_p, W1, g_hh_p,
                                                    att_src1, att_dst1, N);
    agg_kernel<true><<<(N * 32 + 255) / 256, 256>>>(g_hh_p, b1, g_pool_p, N);
    final_kernel<<<(N + 255) / 256, 256>>>(gamma1, beta1, Wc, bc, out, N, invn);
    // streams/events intentionally not destroyed: destroying capture-participating
    // resources mid-capture is illegal; leak is a few host handles on non-replay calls.
}

// round 17
// speedup vs baseline: 1.5857x; 1.2283x over previous
#include <cuda_runtime.h>
#include <cuda_bf16.h>
#include <cuda_fp16.h>
#include <math.h>

#define F_DIM   128
#define HEADS   8
#define CH      16
#define MAXN    50048
#define MAXE    860160
#define NEXT    144            // 128 h cols + 8 a_src + 8 a_dst
#define APAD    136            // row stride in halves (8-half pad)

// ---------------- device scratch ----------------
__device__ __half g_hh[MAXN * F_DIM];    // GEMM output in fp16 (gather-optimized)
__device__ float g_t[MAXN * F_DIM];      // layer0 aggregated output (fp32)
__device__ float g_asrc[MAXN * HEADS];
__device__ float g_adst[MAXN * HEADS];
__device__ __half g_w0h[NEXT * F_DIM];   // extended B for layer0: [144][128]
__device__ __half g_w1h[NEXT * F_DIM];
__device__ int   g_deg[MAXN];
__device__ int   g_off[MAXN + 1];
__device__ int   g_cur[MAXN];
__device__ int   g_csr[MAXE];
__device__ int   g_bsum[256];
__device__ float g_pool[MAXN * CH];
__device__ float g_bnsum0[F_DIM];
__device__ float g_bnsq0[F_DIM];
__device__ float g_bnsum1[CH];
__device__ float g_bnsq1[CH];
__device__ float g_bnscale[F_DIM];
__device__ float g_bnshift[F_DIM];

// ---------------- utility kernels ----------------
__global__ void zero_ints(int* p, int n) {
    int i = blockIdx.x * blockDim.x + threadIdx.x;
    if (i < n) p[i] = 0;
}
__global__ void zero_bn_all() {
    int i = threadIdx.x;
    if (i < F_DIM) { g_bnsum0[i] = 0.f; g_bnsq0[i] = 0.f; }
    if (i < CH)    { g_bnsum1[i] = 0.f; g_bnsq1[i] = 0.f; }
}

// ---------------- prep: build extended fp16 B = [W^T | Wa_src | Wa_dst] ------
__global__ void prep_w(const float* __restrict__ W,
                       const float* __restrict__ aS,
                       const float* __restrict__ aD,
                       __half* __restrict__ outp) {
    int idx = blockIdx.x * 256 + threadIdx.x;
    if (idx >= NEXT * F_DIM) return;
    int n = idx >> 7, k = idx & 127;
    float v;
    if (n < 128) {
        v = W[k * 128 + n];
    } else if (n < 136) {
        int h = n - 128;
        float s = 0.f;
#pragma unroll
        for (int c = 0; c < CH; c++) s += W[k * 128 + h * CH + c] * aS[h * CH + c];
        v = s;
    } else {
        int h = n - 136;
        float s = 0.f;
#pragma unroll
        for (int c = 0; c < CH; c++) s += W[k * 128 + h * CH + c] * aD[h * CH + c];
        v = s;
    }
    outp[n * 128 + k] = __float2half(v);
}

// ---------------- CSR build ----------------
__global__ void hist_kernel(const int* __restrict__ ei, int E, int n) {
    int i = blockIdx.x * blockDim.x + threadIdx.x;
    int tot = E + n;
    if (i >= tot) return;
    int d = (i < E) ? ei[E + i] : (i - E);
    atomicAdd(&g_deg[d], 1);
}

__global__ void scan_p1(int n) {
    __shared__ int ws[8];
    int tid = threadIdx.x;
    int i = blockIdx.x * 256 + tid;
    int v = (i < n) ? g_deg[i] : 0;
    int s = v;
#pragma unroll
    for (int o = 16; o; o >>= 1) s += __shfl_xor_sync(0xFFFFFFFFu, s, o);
    if ((tid & 31) == 0) ws[tid >> 5] = s;
    __syncthreads();
    if (tid < 8) {
        int t = ws[tid];
#pragma unroll
        for (int o = 4; o; o >>= 1) t += __shfl_xor_sync(0xFFu, t, o);
        if (tid == 0) g_bsum[blockIdx.x] = t;
    }
}

__global__ void scan_p2(int nb, int n) {
    __shared__ int ws[8];
    int tid = threadIdx.x;
    int lane = tid & 31, wid = tid >> 5;
    int v = (tid < nb) ? g_bsum[tid] : 0;
    int incl = v;
#pragma unroll
    for (int o = 1; o < 32; o <<= 1) {
        int t = __shfl_up_sync(0xFFFFFFFFu, incl, o);
        if (lane >= o) incl += t;
    }
    if (lane == 31) ws[wid] = incl;
    __syncthreads();
    if (wid == 0) {
        int w = (lane < 8) ? ws[lane] : 0;
#pragma unroll
        for (int o = 1; o < 8; o <<= 1) {
            int t = __shfl_up_sync(0xFFFFFFFFu, w, o);
            if (lane >= o) w += t;
        }
        if (lane < 8) ws[lane] = w;
    }
    __syncthreads();
    int total_excl = incl - v + (wid ? ws[wid - 1] : 0);
    if (tid < nb) g_bsum[tid] = total_excl;
    if (tid == 255) g_off[n] = ws[7];
}

__global__ void scan_p3(int n) {
    __shared__ int ws[8];
    int tid = threadIdx.x;
    int lane = tid & 31, wid = tid >> 5;
    int i = blockIdx.x * 256 + tid;
    int v = (i < n) ? g_deg[i] : 0;
    int incl = v;
#pragma unroll
    for (int o = 1; o < 32; o <<= 1) {
        int t = __shfl_up_sync(0xFFFFFFFFu, incl, o);
        if (lane >= o) incl += t;
    }
    if (lane == 31) ws[wid] = incl;
    __syncthreads();
    if (wid == 0) {
        int w = (lane < 8) ? ws[lane] : 0;
#pragma unroll
        for (int o = 1; o < 8; o <<= 1) {
            int t = __shfl_up_sync(0xFFFFFFFFu, w, o);
            if (lane >= o) w += t;
        }
        if (lane < 8) ws[lane] = w;
    }
    __syncthreads();
    int excl = incl - v + (wid ? ws[wid - 1] : 0) + g_bsum[blockIdx.x];
    if (i < n) { g_off[i] = excl; g_cur[i] = excl; }
}

__global__ void scatter_kernel(const int* __restrict__ ei, int E, int n) {
    int i = blockIdx.x * blockDim.x + threadIdx.x;
    int tot = E + n;
    if (i >= tot) return;
    int s, d;
    if (i < E) { s = ei[i]; d = ei[E + i]; }
    else       { s = d = i - E; }
    int p = atomicAdd(&g_cur[d], 1);
    g_csr[p] = s;
}

// ---------------- BN+ELU helper ----------------
__device__ __forceinline__ float bnelu_f(float v, int f) {
    float y = v * g_bnscale[f] + g_bnshift[f];
    return (y > 0.f) ? y : expm1f(y);
}

// ---------------- tensor-core GEMM (m16n8k16 fp16, fp32 acc) ------------------
// D[M,144] = act(A)[M,128] @ Bext[128,144]; writes h fp16 + a_src/a_dst fp32.
__device__ __forceinline__ void mma16816(float& c0, float& c1, float& c2, float& c3,
                                         unsigned a0, unsigned a1, unsigned a2, unsigned a3,
                                         unsigned b0, unsigned b1) {
    asm volatile(
        "mma.sync.aligned.m16n8k16.row.col.f32.f16.f16.f32 "
        "{%0,%1,%2,%3}, {%4,%5,%6,%7}, {%8,%9}, {%0,%1,%2,%3};"
        : "+f"(c0), "+f"(c1), "+f"(c2), "+f"(c3)
        : "r"(a0), "r"(a1), "r"(a2), "r"(a3), "r"(b0), "r"(b1));
}

#define MMA_SMEM ((128 * APAD + NEXT * APAD) * 2)

template <bool BNELU>
__global__ __launch_bounds__(256, 2) void gemm_mma(
    const float* __restrict__ A, const __half* __restrict__ Bext,
    __half* __restrict__ Ch, int M)
{
    extern __shared__ __half sh[];
    __half* Ah = sh;                    // [128][APAD]
    __half* Bt = sh + 128 * APAD;       // [144][APAD]   Bt[n][k] = Bext_col n
    int tid = threadIdx.x;
    int row0 = blockIdx.x * 128;

    // fill Bt (144*128 halves = 2304 uint4)
    for (int i = tid; i < NEXT * 16; i += 256) {
        int rrow = i >> 4, c8 = (i & 15) << 3;
        *(uint4*)(Bt + rrow * APAD + c8) = *(const uint4*)(Bext + rrow * 128 + c8);
    }
    // fill Ah: fp32 -> (BN+ELU) -> fp16
    for (int i = tid * 4; i < 128 * 128; i += 1024) {
        int r = i >> 7, c = i & 127;
        float4 v = make_float4(0.f, 0.f, 0.f, 0.f);
        if (row0 + r < M) v = *(const float4*)(A + (size_t)(row0 + r) * 128 + c);
        if (BNELU) {
            v.x = bnelu_f(v.x, c + 0); v.y = bnelu_f(v.y, c + 1);
            v.z = bnelu_f(v.z, c + 2); v.w = bnelu_f(v.w, c + 3);
        }
        __half2 h0 = __floats2half2_rn(v.x, v.y);
        __half2 h1 = __floats2half2_rn(v.z, v.w);
        uint2 pk;
        pk.x = *(unsigned*)&h0; pk.y = *(unsigned*)&h1;
        *(uint2*)(Ah + r * APAD + c) = pk;
    }
    __syncthreads();

    int warp = tid >> 5, lane = tid & 31;
    int g = lane >> 2, t4 = lane & 3;
    int mr = warp * 16;

    float acc[18][4];
#pragma unroll
    for (int nt = 0; nt < 18; nt++)
#pragma unroll
        for (int j = 0; j < 4; j++) acc[nt][j] = 0.f;

#pragma unroll
    for (int ks = 0; ks < 8; ks++) {
        int k0 = ks * 16;
        const __half* ar0 = Ah + (mr + g) * APAD + k0 + t4 * 2;
        const __half* ar1 = ar0 + 8 * APAD;
        unsigned a0 = *(const unsigned*)(ar0);
        unsigned a1 = *(const unsigned*)(ar1);
        unsigned a2 = *(const unsigned*)(ar0 + 8);
        unsigned a3 = *(const unsigned*)(ar1 + 8);
#pragma unroll
        for (int nt = 0; nt < 18; nt++) {
            const __half* br = Bt + (nt * 8 + g) * APAD + k0 + t4 * 2;
            unsigned b0 = *(const unsigned*)(br);
            unsigned b1 = *(const unsigned*)(br + 8);
            mma16816(acc[nt][0], acc[nt][1], acc[nt][2], acc[nt][3],
                     a0, a1, a2, a3, b0, b1);
        }
    }

    // epilogue: h (fp16) + scores (fp32)
    int r0 = row0 + mr + g;
    int r1 = r0 + 8;
#pragma unroll
    for (int nt = 0; nt < 16; nt++) {
        int c = nt * 8 + t4 * 2;
        if (r0 < M) {
            __half2 p = __floats2half2_rn(acc[nt][0], acc[nt][1]);
            *(__half2*)(Ch + (size_t)r0 * F_DIM + c) = p;
        }
        if (r1 < M) {
            __half2 p = __floats2half2_rn(acc[nt][2], acc[nt][3]);
            *(__half2*)(Ch + (size_t)r1 * F_DIM + c) = p;
        }
    }
    if (r0 < M) {
        *(float2*)(g_asrc + r0 * HEADS + t4 * 2) = make_float2(acc[16][0], acc[16][1]);
        *(float2*)(g_adst + r0 * HEADS + t4 * 2) = make_float2(acc[17][0], acc[17][1]);
    }
    if (r1 < M) {
        *(float2*)(g_asrc + r1 * HEADS + t4 * 2) = make_float2(acc[16][2], acc[16][3]);
        *(float2*)(g_adst + r1 * HEADS + t4 * 2) = make_float2(acc[17][2], acc[17][3]);
    }
}

// ---------------- single-pass softmax + aggregation + fused BN stats ----------
template <bool MEAN_HEADS>
__global__ void agg_kernel(const __half* __restrict__ h,
                           const float* __restrict__ bias,
                           float* __restrict__ out, int n) {
    __shared__ float s_sum[MEAN_HEADS ? CH : F_DIM];
    __shared__ float s_sq[MEAN_HEADS ? CH : F_DIM];
    const int NF = MEAN_HEADS ? CH : F_DIM;
    int tid = threadIdx.x;
    if (tid < NF) { s_sum[tid] = 0.f; s_sq[tid] = 0.f; }
    __syncthreads();

    int warp = (blockIdx.x * blockDim.x + tid) >> 5;
    int lane = tid & 31;
    int node = warp;
    int head = lane >> 2;
    int fo = lane * 4;

    if (node < n) {
        int beg = g_off[node];
        int end = g_off[node + 1];
        float adst_v = g_adst[node * HEADS + head];

        float ssum = 0.f;
        float4 acc = make_float4(0.f, 0.f, 0.f, 0.f);
        for (int i = beg; i < end; i++) {
            int s = g_csr[i];
            float e = g_asrc[s * HEADS + head] + adst_v;
            e = (e > 0.f) ? e : 0.2f * e;
            float w = __expf(e);
            ssum += w;
            uint2 raw = *(const uint2*)(h + (size_t)s * F_DIM + fo);
            float2 f01 = __half22float2(*(__half2*)&raw.x);
            float2 f23 = __half22float2(*(__half2*)&raw.y);
            acc.x += w * f01.x;
            acc.y += w * f01.y;
            acc.z += w * f23.x;
            acc.w += w * f23.y;
        }
        float inv = 1.0f / (ssum + 1e-16f);
        acc.x *= inv; acc.y *= inv; acc.z *= inv; acc.w *= inv;

        if (MEAN_HEADS) {
#pragma unroll
            for (int o = 4; o < 32; o <<= 1) {
                acc.x += __shfl_xor_sync(0xFFFFFFFFu, acc.x, o);
                acc.y += __shfl_xor_sync(0xFFFFFFFFu, acc.y, o);
                acc.z += __shfl_xor_sync(0xFFFFFFFFu, acc.z, o);
                acc.w += __shfl_xor_sync(0xFFFFFFFFu, acc.w, o);
            }
            if (lane < 4) {
                int cbase = lane * 4;
                float4 r;
                r.x = acc.x * 0.125f + __ldg(&bias[cbase + 0]);
                r.y = acc.y * 0.125f + __ldg(&bias[cbase + 1]);
                r.z = acc.z * 0.125f + __ldg(&bias[cbase + 2]);
                r.w = acc.w * 0.125f + __ldg(&bias[cbase + 3]);
                *(float4*)(out + (size_t)node * CH + cbase) = r;
                atomicAdd(&s_sum[cbase + 0], r.x);
                atomicAdd(&s_sum[cbase + 1], r.y);
                atomicAdd(&s_sum[cbase + 2], r.z);
                atomicAdd(&s_sum[cbase + 3], r.w);
                atomicAdd(&s_sq[cbase + 0], r.x * r.x);
                atomicAdd(&s_sq[cbase + 1], r.y * r.y);
                atomicAdd(&s_sq[cbase + 2], r.z * r.z);
                atomicAdd(&s_sq[cbase + 3], r.w * r.w);
            }
        } else {
            float4 r;
            r.x = acc.x + __ldg(&bias[fo + 0]);
            r.y = acc.y + __ldg(&bias[fo + 1]);
            r.z = acc.z + __ldg(&bias[fo + 2]);
            r.w = acc.w + __ldg(&bias[fo + 3]);
            *(float4*)(out + (size_t)node * F_DIM + fo) = r;
            atomicAdd(&s_sum[fo + 0], r.x);
            atomicAdd(&s_sum[fo + 1], r.y);
            atomicAdd(&s_sum[fo + 2], r.z);
            atomicAdd(&s_sum[fo + 3], r.w);
            atomicAdd(&s_sq[fo + 0], r.x * r.x);
            atomicAdd(&s_sq[fo + 1], r.y * r.y);
            atomicAdd(&s_sq[fo + 2], r.z * r.z);
            atomicAdd(&s_sq[fo + 3], r.w * r.w);
        }
    }
    __syncthreads();
    if (tid < NF) {
        if (MEAN_HEADS) {
            atomicAdd(&g_bnsum1[tid], s_sum[tid]);
            atomicAdd(&g_bnsq1[tid], s_sq[tid]);
        } else {
            atomicAdd(&g_bnsum0[tid], s_sum[tid]);
            atomicAdd(&g_bnsq0[tid], s_sq[tid]);
        }
    }
}

// ---------------- BN finalize: precompute scale/shift (layer0) ----------------
__global__ void bn_finalize(const float* __restrict__ gamma,
                            const float* __restrict__ beta, float invn) {
    int f = threadIdx.x;
    float mu = g_bnsum0[f] * invn;
    float var = g_bnsq0[f] * invn - mu * mu;
    float sc = rsqrtf(var + 1e-5f) * gamma[f];
    g_bnscale[f] = sc;
    g_bnshift[f] = beta[f] - mu * sc;
}

// ---------------- final: BN(F=16) + classifier [16x2] ----------------
__global__ void final_kernel(const float* __restrict__ gamma,
                             const float* __restrict__ beta,
                             const float* __restrict__ Wc,
                             const float* __restrict__ bc,
                             float* __restrict__ out, int n, float invn) {
    int node = blockIdx.x * blockDim.x + threadIdx.x;
    if (node >= n) return;
    float l0 = __ldg(&bc[0]);
    float l1 = __ldg(&bc[1]);
#pragma unroll
    for (int c = 0; c < CH; c++) {
        float mu = g_bnsum1[c] * invn;
        float var = g_bnsq1[c] * invn - mu * mu;
        float sc = rsqrtf(var + 1e-5f) * __ldg(&gamma[c]);
        float y = (g_pool[(size_t)node * CH + c] - mu) * sc + __ldg(&beta[c]);
        l0 += y * __ldg(&Wc[c * 2 + 0]);
        l1 += y * __ldg(&Wc[c * 2 + 1]);
    }
    out[node * 2 + 0] = l0;
    out[node * 2 + 1] = l1;
}

// ---------------- launch ----------------
extern "C" void kernel_launch(void* const* d_in, const int* in_sizes, int n_in,
                              void* d_out, int out_size) {
    const float* x        = (const float*)d_in[0];
    const int*   ei       = (const int*)d_in[1];
    const float* W0       = (const float*)d_in[2];
    const float* att_src0 = (const float*)d_in[3];
    const float* att_dst0 = (const float*)d_in[4];
    const float* b0       = (const float*)d_in[5];
    const float* gamma0   = (const float*)d_in[6];
    const float* beta0    = (const float*)d_in[7];
    const float* W1       = (const float*)d_in[8];
    const float* att_src1 = (const float*)d_in[9];
    const float* att_dst1 = (const float*)d_in[10];
    const float* b1       = (const float*)d_in[11];
    const float* gamma1   = (const float*)d_in[12];
    const float* beta1    = (const float*)d_in[13];
    const float* Wc       = (const float*)d_in[14];
    const float* bc       = (const float*)d_in[15];
    float* out = (float*)d_out;

    int N = in_sizes[0] / F_DIM;
    int E = in_sizes[1] / 2;
    int ET = E + N;
    int NB = (N + 255) / 256;
    float invn = 1.0f / (float)N;

    __half *g_hh_p, *g_w0h_p, *g_w1h_p;
    float *g_t_p, *g_pool_p;
    int *g_deg_p;
    cudaGetSymbolAddress((void**)&g_hh_p, g_hh);
    cudaGetSymbolAddress((void**)&g_w0h_p, g_w0h);
    cudaGetSymbolAddress((void**)&g_w1h_p, g_w1h);
    cudaGetSymbolAddress((void**)&g_t_p, g_t);
    cudaGetSymbolAddress((void**)&g_pool_p, g_pool);
    cudaGetSymbolAddress((void**)&g_deg_p, g_deg);

    cudaFuncSetAttribute(gemm_mma<false>,
                         cudaFuncAttributeMaxDynamicSharedMemorySize, MMA_SMEM);
    cudaFuncSetAttribute(gemm_mma<true>,
                         cudaFuncAttributeMaxDynamicSharedMemorySize, MMA_SMEM);

    int gemm_grid = (N + 127) / 128;
    int prep_grid = (NEXT * F_DIM + 255) / 256;

    // side stream for CSR build + stat zeroing, forked/joined with events
    cudaStream_t s2;
    cudaStreamCreateWithFlags(&s2, cudaStreamNonBlocking);
    cudaEvent_t evFork, evJoin;
    cudaEventCreateWithFlags(&evFork, cudaEventDisableTiming);
    cudaEventCreateWithFlags(&evJoin, cudaEventDisableTiming);

    cudaEventRecord(evFork, 0);
    cudaStreamWaitEvent(s2, evFork, 0);

    // ---- CSR build + BN-stat zero on side stream ----
    zero_ints<<<(N + 255) / 256, 256, 0, s2>>>(g_deg_p, N);
    zero_bn_all<<<1, 256, 0, s2>>>();
    hist_kernel<<<(ET + 255) / 256, 256, 0, s2>>>(ei, E, N);
    scan_p1<<<NB, 256, 0, s2>>>(N);
    scan_p2<<<1, 256, 0, s2>>>(NB, N);
    scan_p3<<<NB, 256, 0, s2>>>(N);
    scatter_kernel<<<(ET + 255) / 256, 256, 0, s2>>>(ei, E, N);
    cudaEventRecord(evJoin, s2);

    // ---- weight prep (tiny) then layer 0 GEMM on main stream ----
    prep_w<<<prep_grid, 256>>>(W0, att_src0, att_dst0, g_w0h_p);
    prep_w<<<prep_grid, 256>>>(W1, att_src1, att_dst1, g_w1h_p);
    gemm_mma<false><<<gemm_grid, 256, MMA_SMEM>>>(x, g_w0h_p, g_hh_p, N);
    cudaStreamWaitEvent(0, evJoin, 0);   // join: agg needs CSR + zeroed stats
    agg_kernel<false><<<(N * 32 + 255) / 256, 256>>>(g_hh_p, b0, g_t_p, N);
    bn_finalize<<<1, F_DIM>>>(gamma0, beta0, invn);

    // ---- layer 1: GEMM (BN+ELU fused on A load) -> agg -> final ----
    gemm_mma<true><<<gemm_grid, 256, MMA_SMEM>>>(g_t_p, g_w1h_p, g_hh_p, N);
    agg_kernel<true><<<(N * 32 + 255) / 256, 256>>>(g_hh_p, b1, g_pool_p, N);
    final_kernel<<<(N + 255) / 256, 256>>>(gamma1, beta1, Wc, bc, out, N, invn);
    // streams/events intentionally not destroyed: destroying capture-participating
    // resources mid-capture is illegal; leak is a few host handles on non-replay calls.
}